// round 17
// baseline (speedup 1.0000x reference)
#include <cuda_runtime.h>
#include <cuda_bf16.h>
#include <math_constants.h>
#include <cstdint>

#define BS 8
#define NQ 1000
#define D 256
#define NROWS (BS * NQ)
#define TOPK 10
#define MAX_PAIRS (NROWS * TOPK)
#define MROWS 10      // rows per block in mask kernel
#define GROUP 32      // rows/pairs per group in GEMM kernels
#define AST 132       // words per X-plane row (128 + 4 pad -> conflict-free)
#define WST 136       // words per W-buffer row (128 + 8 pad -> conflict-free)
#define KC 32         // k-values per staged chunk
#define NCHUNK (D / KC)      // 8
#define WBUF (32 * WST)      // words per staged W chunk (2 planes x 16 kpairs)
#define XPL (GROUP * AST)    // words per X plane (4224)
#define GRID_G 296
#define SMEM_G ((2 * XPL + 3 * WBUF) * 4)   // 86,016 bytes

// ---------------- scratch (no allocations allowed) ----------------
__device__ float g_H[NROWS * D];        // layer-1 output (active rows)
__device__ float g_Z[NROWS * D];        // layer-2 output (pre-LN)
__device__ float g_P[NROWS * D];        // P = id_token @ W3
__device__ float g_cur[NROWS * D];      // running max of masked features
__device__ __align__(16) uint32_t g_Wbf[5 * 65536];  // bf16 (h,l) planes, k-pair packed
__device__ int   g_pairs[MAX_PAIRS * 2];
__device__ int   g_pair_count;
__device__ int   g_flag[NROWS];
__device__ int   g_idrows[NROWS];
__device__ int   g_nid;
__device__ int   g_outrows[NROWS];
__device__ int   g_nout;

__device__ __forceinline__ void atomicMaxFloat(float* addr, float v) {
    if (v >= 0.0f) atomicMax((int*)addr, __float_as_int(v));
    else           atomicMin((unsigned int*)addr, __float_as_uint(v));
}

// ---------------- bf16 2-split helpers ----------------
__device__ __forceinline__ void split_bf16x2(float x0, float x1,
                                             uint32_t& wh, uint32_t& wl) {
    uint32_t wh_;
    asm("{\n\t.reg .b16 h0, h1;\n\t"
        "cvt.rn.bf16.f32 h0, %1;\n\t"
        "cvt.rn.bf16.f32 h1, %2;\n\t"
        "mov.b32 %0, {h0, h1};\n\t}" : "=r"(wh_) : "f"(x0), "f"(x1));
    const float h0f = __uint_as_float(wh_ << 16);
    const float h1f = __uint_as_float(wh_ & 0xffff0000u);
    const float l0 = x0 - h0f, l1 = x1 - h1f;
    uint32_t wl_;
    asm("{\n\t.reg .b16 p0, p1;\n\t"
        "cvt.rn.bf16.f32 p0, %1;\n\t"
        "cvt.rn.bf16.f32 p1, %2;\n\t"
        "mov.b32 %0, {p0, p1};\n\t}" : "=r"(wl_) : "f"(l0), "f"(l1));
    wh = wh_; wl = wl_;
}

__device__ __forceinline__ void mma_bf16(float c[4],
    uint32_t a0, uint32_t a1, uint32_t a2, uint32_t a3,
    uint32_t b0, uint32_t b1)
{
    asm volatile(
        "mma.sync.aligned.m16n8k16.row.col.f32.bf16.bf16.f32 "
        "{%0,%1,%2,%3}, {%4,%5,%6,%7}, {%8,%9}, {%0,%1,%2,%3};"
        : "+f"(c[0]), "+f"(c[1]), "+f"(c[2]), "+f"(c[3])
        : "r"(a0), "r"(a1), "r"(a2), "r"(a3), "r"(b0), "r"(b1));
}

// ---------------- cp.async helpers ----------------
__device__ __forceinline__ uint32_t smem_u32(const void* p) {
    return (uint32_t)__cvta_generic_to_shared(p);
}
__device__ __forceinline__ void cp16(uint32_t dst, const void* src) {
    asm volatile("cp.async.cg.shared.global [%0], [%1], 16;" :: "r"(dst), "l"(src));
}
__device__ __forceinline__ void cp_commit() {
    asm volatile("cp.async.commit_group;");
}
__device__ __forceinline__ void cp_wait0() {
    asm volatile("cp.async.wait_group 0;");
}
__device__ __forceinline__ void cp_wait1() {
    asm volatile("cp.async.wait_group 1;");
}

// ---------------- prep: reset + convert weights to bf16 planes ----------------
__global__ __launch_bounds__(256) void k_prep(
    const float* __restrict__ W1, const float* __restrict__ W2,
    const float* __restrict__ W3, const float* __restrict__ W4,
    const float* __restrict__ W5)
{
    const int idx = blockIdx.x * 256 + threadIdx.x;
    if (idx < NROWS) g_flag[idx] = 0;
    if (idx == 0) { g_pair_count = 0; g_nid = 0; g_nout = 0; }
    if (idx < 5 * 32768) {
        const int w = idx >> 15, rem = idx & 32767;
        const int kp = rem >> 8, col = rem & 255;
        const float* Wt[5] = {W1, W2, W3, W4, W5};
        const float x0 = Wt[w][(2 * kp) * D + col];
        const float x1 = Wt[w][(2 * kp + 1) * D + col];
        uint32_t wh, wl;
        split_bf16x2(x0, x1, wh, wl);
        g_Wbf[w * 65536 + kp * 256 + col] = wh;
        g_Wbf[w * 65536 + 32768 + kp * 256 + col] = wl;
    }
}

// stage one 32-k chunk (both planes) of one column-half of packed W
// 1024 cp16 segments over 256 threads (4 each)
__device__ __forceinline__ void stage_w(uint32_t* Wbuf, const uint32_t* __restrict__ Wg,
                                        int kc, int ch, int t)
{
#pragma unroll
    for (int i = 0; i < 4; i++) {
        const int idx = t + (i << 8);          // 0..1023
        const int p   = idx >> 9;              // plane
        const int r16 = (idx >> 5) & 15;       // kpair within chunk
        const int sg  = idx & 31;              // 16B segment (4 words)
        cp16(smem_u32(Wbuf + (p * 16 + r16) * WST + (sg << 2)),
             Wg + (size_t)p * 32768 + (kc * 16 + r16) * 256 + (ch << 7) + (sg << 2));
    }
    cp_commit();
}

// Core: C[4][4] = X(32 x 256, bf16 2-split planes) @ W[:, ch*128..+128), bf16x3.
// 8 warps: rg = w&1 (16-row group), cg = w>>1 (32-col group within half).
__device__ __forceinline__ void mma_half(
    const uint32_t* Xsh, const uint32_t* Xsl, uint32_t* Ws,
    const uint32_t* __restrict__ Wg, int ch,
    float C[4][4], int rg, int cg, int g, int tig, int t)
{
#pragma unroll
    for (int nt = 0; nt < 4; nt++)
#pragma unroll
        for (int i = 0; i < 4; i++) C[nt][i] = 0.0f;

    const int row0 = rg * 16 + g;

    stage_w(Ws,        Wg, 0, ch, t);
    stage_w(Ws + WBUF, Wg, 1, ch, t);
    for (int kc = 0; kc < NCHUNK; kc++) {
        if (kc == NCHUNK - 1) cp_wait0(); else cp_wait1();
        __syncthreads();   // chunk kc visible; restaged buffer free; (kc=0) X writes ordered
        if (kc + 2 < NCHUNK) stage_w(Ws + ((kc + 2) % 3) * WBUF, Wg, kc + 2, ch, t);
        const uint32_t* Wb = Ws + (kc % 3) * WBUF;

#pragma unroll
        for (int ks2 = 0; ks2 < 2; ks2++) {
            const int ab = row0 * AST + kc * 16 + ks2 * 8 + tig;
            const uint32_t ah0 = Xsh[ab];
            const uint32_t ah1 = Xsh[ab + 8 * AST];
            const uint32_t ah2 = Xsh[ab + 4];
            const uint32_t ah3 = Xsh[ab + 8 * AST + 4];
            const uint32_t al0 = Xsl[ab];
            const uint32_t al1 = Xsl[ab + 8 * AST];
            const uint32_t al2 = Xsl[ab + 4];
            const uint32_t al3 = Xsl[ab + 8 * AST + 4];

#pragma unroll
            for (int nt = 0; nt < 4; nt++) {
                const int col = cg * 32 + nt * 8 + g;
                const uint32_t bh0 = Wb[(ks2 * 8 + tig) * WST + col];
                const uint32_t bh1 = Wb[(ks2 * 8 + tig + 4) * WST + col];
                const uint32_t bl0 = Wb[(16 + ks2 * 8 + tig) * WST + col];
                const uint32_t bl1 = Wb[(16 + ks2 * 8 + tig + 4) * WST + col];
                mma_bf16(C[nt], ah0, ah1, ah2, ah3, bh0, bh1);
                mma_bf16(C[nt], ah0, ah1, ah2, ah3, bl0, bl1);
                mma_bf16(C[nt], al0, al1, al2, al3, bh0, bh1);
            }
        }
    }
    __syncthreads();   // all warps done before caller reuses X/W regions
}

// stage 32 indexed rows (guarded) as split planes
__device__ __forceinline__ void stage_rows_cvt(uint32_t* Xsh, uint32_t* Xsl,
                                               const float* __restrict__ src,
                                               const int* srow, int t)
{
#pragma unroll
    for (int i = 0; i < 8; i++) {
        const int idx = t + (i << 8);
        const int r = idx >> 6, c4 = (idx & 63) << 2;
        const int rr = srow[r];
        const float4 v = (rr >= 0) ? *(const float4*)(src + (size_t)rr * D + c4)
                                   : make_float4(0.f, 0.f, 0.f, 0.f);
        uint32_t h0, l0, h1, l1;
        split_bf16x2(v.x, v.y, h0, l0);
        split_bf16x2(v.z, v.w, h1, l1);
        const int wi = r * AST + (c4 >> 1);
        *(uint2*)&Xsh[wi] = make_uint2(h0, h1);
        *(uint2*)&Xsl[wi] = make_uint2(l0, l1);
    }
}

// ---------------- K2: IoU mask + selection + cur-init + base output ----------------
__global__ __launch_bounds__(256) void k_mask_sel(
    const float* __restrict__ pred, const float* __restrict__ seed,
    const float* __restrict__ tgt,  const float* __restrict__ b5,
    float* __restrict__ out, float* __restrict__ out_mask)
{
    const int base = blockIdx.x * MROWS;
    const int b = base / NQ;
    const int t = threadIdx.x;

    __shared__ float4 s_box[NQ];
    __shared__ float  s_seed[NQ];
    __shared__ int    s_cnt, s_m;
    __shared__ float  sval[256];
    __shared__ int    sidx[256];
    __shared__ int    s_sel[TOPK];

    const float rb5 = fmaxf(b5[t], 0.0f);

    for (int j = t; j < NQ; j += 256) {
        s_box[j]  = ((const float4*)pred)[b * NQ + j];
        s_seed[j] = seed[b * NQ + j];
    }
    __syncthreads();

    for (int r = 0; r < MROWS; r++) {
        const int row = base + r;
        const int li  = row - b * NQ;
        if (t == 0) s_cnt = 0;
        __syncthreads();

        const float4 pb = s_box[li];
        const float bx1 = __fsub_rn(pb.x, __fmul_rn(0.5f, pb.z));
        const float by1 = __fsub_rn(pb.y, __fmul_rn(0.5f, pb.w));
        const float bx2 = __fadd_rn(pb.x, __fmul_rn(0.5f, pb.z));
        const float by2 = __fadd_rn(pb.y, __fmul_rn(0.5f, pb.w));
        const float ai  = __fmul_rn(__fsub_rn(bx2, bx1), __fsub_rn(by2, by1));
        const bool negi = (s_seed[li] == 0.0f);

        for (int j = t; j < NQ; j += 256) {
            const float4 q = s_box[j];
            const float qx1 = __fsub_rn(q.x, __fmul_rn(0.5f, q.z));
            const float qy1 = __fsub_rn(q.y, __fmul_rn(0.5f, q.w));
            const float qx2 = __fadd_rn(q.x, __fmul_rn(0.5f, q.z));
            const float qy2 = __fadd_rn(q.y, __fmul_rn(0.5f, q.w));
            const float aj  = __fmul_rn(__fsub_rn(qx2, qx1), __fsub_rn(qy2, qy1));
            const float w = fmaxf(__fsub_rn(fminf(bx2, qx2), fmaxf(bx1, qx1)), 0.0f);
            const float h = fmaxf(__fsub_rn(fminf(by2, qy2), fmaxf(by1, qy1)), 0.0f);
            const float inter = __fmul_rn(w, h);
            const float uni = __fsub_rn(__fadd_rn(ai, aj), inter);
            const float iou = __fdiv_rn(inter, uni);
            const bool attn = (iou >= 0.5f);
            out_mask[(size_t)row * NQ + j] = attn ? 1.0f : 0.0f;
            if (attn && negi && (s_seed[j] != 0.0f)) {
                int p = atomicAdd(&s_cnt, 1);
                if (p < 256) { sval[p] = iou; sidx[p] = j; }
            }
        }
        __syncthreads();

        // warp-0 parallel top-K selection (value desc, index asc — matches stable argsort)
        if (t < 32) {
            const int cnt = min(s_cnt, 256);
            const int m = min(cnt, TOPK);
            if (t == 0) s_m = m;
            if (cnt <= TOPK) {
                if (t == 0)
                    for (int q = 0; q < cnt; q++) s_sel[q] = sidx[q];
            } else {
                for (int rr = 0; rr < TOPK; rr++) {
                    __syncwarp();
                    unsigned long long key = 0ull;
                    for (int p = t; p < cnt; p += 32) {
                        const float v = sval[p];
                        if (v >= 0.0f) {
                            const unsigned long long k =
                                ((unsigned long long)__float_as_uint(v) << 32)
                                | (unsigned)(0xFFFFFFFFu - (unsigned)sidx[p]);
                            if (k > key) key = k;
                        }
                    }
#pragma unroll
                    for (int off = 16; off > 0; off >>= 1) {
                        const unsigned long long o = __shfl_xor_sync(0xffffffff, key, off);
                        if (o > key) key = o;
                    }
                    const int jsel = (int)(0xFFFFFFFFu - (unsigned)(key & 0xFFFFFFFFu));
                    __syncwarp();
                    for (int p = t; p < cnt; p += 32)
                        if (sidx[p] == jsel) sval[p] = -1.0f;
                    if (t == 0) s_sel[rr] = jsel;
                }
            }
            __syncwarp();
            if (t == 0 && s_m > 0) {
                const int m2 = s_m;
                int pbase = atomicAdd(&g_pair_count, m2);
                for (int qq = 0; qq < m2; qq++) {
                    g_pairs[2 * (pbase + qq)]     = row;
                    g_pairs[2 * (pbase + qq) + 1] = s_sel[qq];
                    g_flag[b * NQ + s_sel[qq]] = 1;
                }
                g_flag[row] = 1;
                int op = atomicAdd(&g_nout, 1);
                g_outrows[op] = row;
            }
        }
        __syncthreads();
        const int m = s_m;
        if (m == 0) {
            const float neg = 1.0f - s_seed[li];
            out[(size_t)row * D + t] = tgt[(size_t)row * D + t] + rb5 * neg;
        } else {
            g_cur[(size_t)row * D + t] = (m < TOPK) ? 0.0f : -CUDART_INF_F;
        }
    }
}

// ---------------- compaction of id-rows ----------------
__global__ void k_compact() {
    const int i = blockIdx.x * 256 + threadIdx.x;
    if (i < NROWS && g_flag[i]) {
        int p = atomicAdd(&g_nid, 1);
        g_idrows[p] = i;
    }
}

// ---------------- L1: h = relu(tgt@W1 + b1) ----------------
__global__ __launch_bounds__(256, 2) void k_l1(
    const float* __restrict__ tgt, const float* __restrict__ b1)
{
    extern __shared__ uint32_t sm[];
    uint32_t* Xsh = sm;
    uint32_t* Xsl = sm + XPL;
    uint32_t* Ws  = sm + 2 * XPL;
    __shared__ int srow[GROUP];

    const int t = threadIdx.x;
    const int w = t >> 5, lane = t & 31;
    const int rg = w & 1, cg = w >> 1;
    const int g = lane >> 2, tig = lane & 3;
    const int nact = g_nid;
    const int units = ((nact + GROUP - 1) / GROUP) * 2;

    for (int u = blockIdx.x; u < units; u += gridDim.x) {
        const int g0 = (u >> 1) * GROUP;
        const int ch = u & 1;
        if (t < GROUP) srow[t] = (g0 + t < nact) ? g_idrows[g0 + t] : -1;
        __syncthreads();
        stage_rows_cvt(Xsh, Xsl, tgt, srow, t);

        float C[4][4];
        mma_half(Xsh, Xsl, Ws, g_Wbf, ch, C, rg, cg, g, tig, t);

#pragma unroll
        for (int nt = 0; nt < 4; nt++) {
            const int col = ch * 128 + cg * 32 + nt * 8 + (tig << 1);
            const float2 bb = *(const float2*)(b1 + col);
            const int r0 = rg * 16 + g, r1 = r0 + 8;
            const int rw0 = srow[r0], rw1 = srow[r1];
            if (rw0 >= 0)
                *(float2*)(g_H + (size_t)rw0 * D + col) =
                    make_float2(fmaxf(C[nt][0] + bb.x, 0.f), fmaxf(C[nt][1] + bb.y, 0.f));
            if (rw1 >= 0)
                *(float2*)(g_H + (size_t)rw1 * D + col) =
                    make_float2(fmaxf(C[nt][2] + bb.x, 0.f), fmaxf(C[nt][3] + bb.y, 0.f));
        }
        __syncthreads();
    }
}

// ---------------- L2: z = h@W2 + b2 ----------------
__global__ __launch_bounds__(256, 2) void k_l2(const float* __restrict__ b2)
{
    extern __shared__ uint32_t sm[];
    uint32_t* Xsh = sm;
    uint32_t* Xsl = sm + XPL;
    uint32_t* Ws  = sm + 2 * XPL;
    __shared__ int srow[GROUP];

    const int t = threadIdx.x;
    const int w = t >> 5, lane = t & 31;
    const int rg = w & 1, cg = w >> 1;
    const int g = lane >> 2, tig = lane & 3;
    const int nact = g_nid;
    const int units = ((nact + GROUP - 1) / GROUP) * 2;

    for (int u = blockIdx.x; u < units; u += gridDim.x) {
        const int g0 = (u >> 1) * GROUP;
        const int ch = u & 1;
        if (t < GROUP) srow[t] = (g0 + t < nact) ? g_idrows[g0 + t] : -1;
        __syncthreads();
        stage_rows_cvt(Xsh, Xsl, g_H, srow, t);

        float C[4][4];
        mma_half(Xsh, Xsl, Ws, g_Wbf + 65536, ch, C, rg, cg, g, tig, t);

#pragma unroll
        for (int nt = 0; nt < 4; nt++) {
            const int col = ch * 128 + cg * 32 + nt * 8 + (tig << 1);
            const float2 bb = *(const float2*)(b2 + col);
            const int r0 = rg * 16 + g, r1 = r0 + 8;
            const int rw0 = srow[r0], rw1 = srow[r1];
            if (rw0 >= 0)
                *(float2*)(g_Z + (size_t)rw0 * D + col) =
                    make_float2(C[nt][0] + bb.x, C[nt][1] + bb.y);
            if (rw1 >= 0)
                *(float2*)(g_Z + (size_t)rw1 * D + col) =
                    make_float2(C[nt][2] + bb.x, C[nt][3] + bb.y);
        }
        __syncthreads();
    }
}

// ---------------- L3: P = (LN(z)*g2+be2) @ W3 ----------------
__global__ __launch_bounds__(256, 2) void k_l3(
    const float* __restrict__ g2, const float* __restrict__ be2)
{
    extern __shared__ uint32_t sm[];
    uint32_t* Xsh = sm;
    uint32_t* Xsl = sm + XPL;
    uint32_t* Ws  = sm + 2 * XPL;
    __shared__ int srow[GROUP];
    __shared__ float s_mean[GROUP], s_rstd[GROUP];

    const int t = threadIdx.x;
    const int w = t >> 5, lane = t & 31;
    const int rg = w & 1, cg = w >> 1;
    const int g = lane >> 2, tig = lane & 3;
    const int nact = g_nid;
    const int units = ((nact + GROUP - 1) / GROUP) * 2;

    for (int u = blockIdx.x; u < units; u += gridDim.x) {
        const int g0 = (u >> 1) * GROUP;
        const int ch = u & 1;
        if (t < GROUP) srow[t] = (g0 + t < nact) ? g_idrows[g0 + t] : -1;
        __syncthreads();

        // LN stats straight from global: warp w rows 4w..4w+3
        for (int rr = (w << 2); rr < (w << 2) + 4; rr++) {
            const int row = srow[rr];
            float s = 0.f, sq = 0.f;
            if (row >= 0) {
#pragma unroll
                for (int i = 0; i < 2; i++) {
                    const float4 v = *(const float4*)(g_Z + (size_t)row * D + (lane << 2) + (i << 7));
                    s += v.x + v.y + v.z + v.w;
                    sq += v.x * v.x + v.y * v.y + v.z * v.z + v.w * v.w;
                }
            }
#pragma unroll
            for (int off = 16; off > 0; off >>= 1) {
                s  += __shfl_down_sync(0xffffffff, s,  off);
                sq += __shfl_down_sync(0xffffffff, sq, off);
            }
            if (lane == 0) {
                const float m = s * (1.0f / D);
                s_mean[rr] = m;
                s_rstd[rr] = rsqrtf(sq * (1.0f / D) - m * m + 1e-5f);
            }
        }
        __syncthreads();

        // stage rows with LN transform applied, converting to planes
#pragma unroll
        for (int i = 0; i < 8; i++) {
            const int idx = t + (i << 8);
            const int r = idx >> 6, c4 = (idx & 63) << 2;
            const int rr = srow[r];
            float4 v = make_float4(0.f, 0.f, 0.f, 0.f);
            if (rr >= 0) {
                const float4 z = *(const float4*)(g_Z + (size_t)rr * D + c4);
                const float4 gv = *(const float4*)(g2 + c4);
                const float4 bv = *(const float4*)(be2 + c4);
                const float m = s_mean[r], rs = s_rstd[r];
                v.x = (z.x - m) * rs * gv.x + bv.x;
                v.y = (z.y - m) * rs * gv.y + bv.y;
                v.z = (z.z - m) * rs * gv.z + bv.z;
                v.w = (z.w - m) * rs * gv.w + bv.w;
            }
            uint32_t h0, l0, h1, l1;
            split_bf16x2(v.x, v.y, h0, l0);
            split_bf16x2(v.z, v.w, h1, l1);
            const int wi = r * AST + (c4 >> 1);
            *(uint2*)&Xsh[wi] = make_uint2(h0, h1);
            *(uint2*)&Xsl[wi] = make_uint2(l0, l1);
        }

        float C[4][4];
        mma_half(Xsh, Xsl, Ws, g_Wbf + 2 * 65536, ch, C, rg, cg, g, tig, t);

#pragma unroll
        for (int nt = 0; nt < 4; nt++) {
            const int col = ch * 128 + cg * 32 + nt * 8 + (tig << 1);
            const int r0 = rg * 16 + g, r1 = r0 + 8;
            const int rw0 = srow[r0], rw1 = srow[r1];
            if (rw0 >= 0)
                *(float2*)(g_P + (size_t)rw0 * D + col) = make_float2(C[nt][0], C[nt][1]);
            if (rw1 >= 0)
                *(float2*)(g_P + (size_t)rw1 * D + col) = make_float2(C[nt][2], C[nt][3]);
        }
        __syncthreads();
    }
}

// ---------------- L4: per-pair relu(P_i-P_j+b3)@W4+b4 -> seg-max + atomic ----------------
__global__ __launch_bounds__(256, 2) void k_l4(
    const float* __restrict__ b3, const float* __restrict__ b4)
{
    extern __shared__ uint32_t sm[];
    uint32_t* Xsh = sm;
    uint32_t* Xsl = sm + XPL;
    uint32_t* Ws  = sm + 2 * XPL;
    float* scratch = (float*)sm;   // reused after MMA for feature dump
    __shared__ int spr[GROUP], sjj[GROUP];

    const int t = threadIdx.x;
    const int w = t >> 5, lane = t & 31;
    const int rg = w & 1, cg = w >> 1;
    const int g = lane >> 2, tig = lane & 3;
    const int npairs = g_pair_count;
    const int units = ((npairs + GROUP - 1) / GROUP) * 2;

    for (int u = blockIdx.x; u < units; u += gridDim.x) {
        const int g0 = (u >> 1) * GROUP;
        const int ch = u & 1;
        if (t < GROUP) {
            if (g0 + t < npairs) {
                spr[t] = g_pairs[2 * (g0 + t)];
                sjj[t] = g_pairs[2 * (g0 + t) + 1];
            } else spr[t] = -1;
        }
        __syncthreads();

        // stage X = relu(P_i - P_j + b3), converting to planes
#pragma unroll
        for (int i = 0; i < 8; i++) {
            const int idx = t + (i << 8);
            const int p = idx >> 6, c4 = (idx & 63) << 2;
            const int rp = spr[p];
            float4 v = make_float4(0.f, 0.f, 0.f, 0.f);
            if (rp >= 0) {
                const int jab = (rp / NQ) * NQ + sjj[p];
                const float4 a  = *(const float4*)(g_P + (size_t)rp  * D + c4);
                const float4 nb = *(const float4*)(g_P + (size_t)jab * D + c4);
                const float4 bv = *(const float4*)(b3 + c4);
                v.x = fmaxf(a.x - nb.x + bv.x, 0.f);
                v.y = fmaxf(a.y - nb.y + bv.y, 0.f);
                v.z = fmaxf(a.z - nb.z + bv.z, 0.f);
                v.w = fmaxf(a.w - nb.w + bv.w, 0.f);
            }
            uint32_t h0, l0, h1, l1;
            split_bf16x2(v.x, v.y, h0, l0);
            split_bf16x2(v.z, v.w, h1, l1);
            const int wi = p * AST + (c4 >> 1);
            *(uint2*)&Xsh[wi] = make_uint2(h0, h1);
            *(uint2*)&Xsl[wi] = make_uint2(l0, l1);
        }

        float C[4][4];
        mma_half(Xsh, Xsl, Ws, g_Wbf + 3 * 65536, ch, C, rg, cg, g, tig, t);

        // dump features into scratch (local col within half, stride AST)
#pragma unroll
        for (int nt = 0; nt < 4; nt++) {
            const int colL = cg * 32 + nt * 8 + (tig << 1);
            const int p0 = rg * 16 + g, p1 = p0 + 8;
            *(float2*)(scratch + p0 * AST + colL) = make_float2(C[nt][0], C[nt][1]);
            *(float2*)(scratch + p1 * AST + colL) = make_float2(C[nt][2], C[nt][3]);
        }
        __syncthreads();

        // segmented max: thread t -> local col t&127, pair-range half t>>7
        {
            const int cL = t & 127;
            const int colG = ch * 128 + cL;
            const float bias = b4[colG];
            const int pLo = (t >> 7) << 4;      // 0 or 16
            int curRow = -1; float curMax = 0.f;
            for (int p = pLo; p < pLo + 16; p++) {
                const int rp = spr[p];
                if (rp < 0) break;
                const float v = scratch[p * AST + cL] + bias;
                if (rp != curRow) {
                    if (curRow >= 0) atomicMaxFloat(&g_cur[(size_t)curRow * D + colG], curMax);
                    curRow = rp; curMax = v;
                } else {
                    curMax = fmaxf(curMax, v);
                }
            }
            if (curRow >= 0) atomicMaxFloat(&g_cur[(size_t)curRow * D + colG], curMax);
        }
        __syncthreads();
    }
}

// ---------------- L5: out = tgt + relu(cur@W5+b5) for active rows ----------------
__global__ __launch_bounds__(256, 2) void k_l5(
    const float* __restrict__ tgt, const float* __restrict__ b5,
    float* __restrict__ out)
{
    extern __shared__ uint32_t sm[];
    uint32_t* Xsh = sm;
    uint32_t* Xsl = sm + XPL;
    uint32_t* Ws  = sm + 2 * XPL;
    __shared__ int srow[GROUP];

    const int t = threadIdx.x;
    const int w = t >> 5, lane = t & 31;
    const int rg = w & 1, cg = w >> 1;
    const int g = lane >> 2, tig = lane & 3;
    const int nact = g_nout;
    const int units = ((nact + GROUP - 1) / GROUP) * 2;

    for (int u = blockIdx.x; u < units; u += gridDim.x) {
        const int g0 = (u >> 1) * GROUP;
        const int ch = u & 1;
        if (t < GROUP) srow[t] = (g0 + t < nact) ? g_outrows[g0 + t] : -1;
        __syncthreads();
        stage_rows_cvt(Xsh, Xsl, g_cur, srow, t);

        float C[4][4];
        mma_half(Xsh, Xsl, Ws, g_Wbf + 4 * 65536, ch, C, rg, cg, g, tig, t);

#pragma unroll
        for (int nt = 0; nt < 4; nt++) {
            const int col = ch * 128 + cg * 32 + nt * 8 + (tig << 1);
            const float2 bb = *(const float2*)(b5 + col);
            const int r0 = rg * 16 + g, r1 = r0 + 8;
            const int rw0 = srow[r0], rw1 = srow[r1];
            if (rw0 >= 0) {
                const float2 tg = *(const float2*)(tgt + (size_t)rw0 * D + col);
                *(float2*)(out + (size_t)rw0 * D + col) =
                    make_float2(tg.x + fmaxf(C[nt][0] + bb.x, 0.f),
                                tg.y + fmaxf(C[nt][1] + bb.y, 0.f));
            }
            if (rw1 >= 0) {
                const float2 tg = *(const float2*)(tgt + (size_t)rw1 * D + col);
                *(float2*)(out + (size_t)rw1 * D + col) =
                    make_float2(tg.x + fmaxf(C[nt][2] + bb.x, 0.f),
                                tg.y + fmaxf(C[nt][3] + bb.y, 0.f));
            }
        }
        __syncthreads();
    }
}

// ---------------- launch ----------------
extern "C" void kernel_launch(void* const* d_in, const int* in_sizes, int n_in,
                              void* d_out, int out_size) {
    const float* tgt  = (const float*)d_in[0];
    const float* seed = (const float*)d_in[1];
    const float* pred = (const float*)d_in[2];
    const float* W1 = (const float*)d_in[3];  const float* b1 = (const float*)d_in[4];
    const float* W2 = (const float*)d_in[5];  const float* b2 = (const float*)d_in[6];
    const float* g2 = (const float*)d_in[7];  const float* be2 = (const float*)d_in[8];
    const float* W3 = (const float*)d_in[9];  const float* b3 = (const float*)d_in[10];
    const float* W4 = (const float*)d_in[11]; const float* b4 = (const float*)d_in[12];
    const float* W5 = (const float*)d_in[13]; const float* b5 = (const float*)d_in[14];

    float* out = (float*)d_out;                 // cur_tgt: 8*1000*256 floats
    float* out_mask = out + (size_t)NROWS * D;  // attn_mask: 8*1000*1000 floats

    cudaFuncSetAttribute(k_l1, cudaFuncAttributeMaxDynamicSharedMemorySize, SMEM_G);
    cudaFuncSetAttribute(k_l2, cudaFuncAttributeMaxDynamicSharedMemorySize, SMEM_G);
    cudaFuncSetAttribute(k_l3, cudaFuncAttributeMaxDynamicSharedMemorySize, SMEM_G);
    cudaFuncSetAttribute(k_l4, cudaFuncAttributeMaxDynamicSharedMemorySize, SMEM_G);
    cudaFuncSetAttribute(k_l5, cudaFuncAttributeMaxDynamicSharedMemorySize, SMEM_G);

    k_prep<<<(5 * 32768 + 255) / 256, 256>>>(W1, W2, W3, W4, W5);
    k_mask_sel<<<NROWS / MROWS, 256>>>(pred, seed, tgt, b5, out, out_mask);
    k_compact<<<(NROWS + 255) / 256, 256>>>();
    k_l1<<<GRID_G, 256, SMEM_G>>>(tgt, b1);
    k_l2<<<GRID_G, 256, SMEM_G>>>(b2);
    k_l3<<<GRID_G, 256, SMEM_G>>>(g2, be2);
    k_l4<<<GRID_G, 256, SMEM_G>>>(b3, b4);
    k_l5<<<GRID_G, 256, SMEM_G>>>(tgt, b5, out);
}